// round 11
// baseline (speedup 1.0000x reference)
#include <cuda_runtime.h>
#include <cuda_fp16.h>
#include <cstdint>

#define H_RES 150
#define CAP   2000000
#define NB    262144      // sort buckets: t7|x4|y4|z3

// Transposed fp16 planes: per scale s (W = 64<<s), layout [3, H, W, 16] halfs.
__device__ __align__(16) __half g_planes_h[6912000];
__device__ __align__(16) float4 g_pts_sorted[CAP];
__device__ int g_keys[CAP];
__device__ int g_idx[CAP];
__device__ int g_hist[NB];     // zeroed at load; re-zeroed by scatter each replay
__device__ int g_bsum[1024];
__device__ int g_offs[NB];

// smem words: fp16 weights [0,16384); per-pair buf [32][68] at 16384 + pair*2176
#define OFF_BUF    16384
#define BUF_STRIDE 68
#define PAIR_WORDS 2176
#define SM_BYTES   135168

__device__ __forceinline__ uint32_t h2_of(float a, float b) {
    __half2 h = __float22half2_rn(make_float2(a, b));   // .x = low half
    return *(uint32_t*)&h;
}

__device__ __forceinline__ void mma16(float d[4], uint32_t a0, uint32_t a1,
                                      uint32_t a2, uint32_t a3,
                                      uint32_t b0, uint32_t b1) {
    asm volatile(
        "mma.sync.aligned.m16n8k16.row.col.f32.f16.f16.f32 "
        "{%0,%1,%2,%3}, {%4,%5,%6,%7}, {%8,%9}, {%0,%1,%2,%3};"
        : "+f"(d[0]), "+f"(d[1]), "+f"(d[2]), "+f"(d[3])
        : "r"(a0), "r"(a1), "r"(a2), "r"(a3), "r"(b0), "r"(b1));
}

// GEMM over 2 m16 tiles and a half-N slice (verified R8/R10 code).
template<int KC, int NTT, int NTH>
__device__ __forceinline__ void gemm2m(const uint32_t* __restrict__ A,
                                       const uint2* __restrict__ Wp,
                                       int g, int q, int lane, float acc[2][NTH][4]) {
#pragma unroll
    for (int mt = 0; mt < 2; mt++)
#pragma unroll
        for (int n8 = 0; n8 < NTH; n8++)
#pragma unroll
            for (int i = 0; i < 4; i++) acc[mt][n8][i] = 0.f;

    const uint32_t* r0lo = A + g * BUF_STRIDE;
    const uint32_t* r0hi = A + (g + 8) * BUF_STRIDE;
    const uint32_t* r1lo = A + (g + 16) * BUF_STRIDE;
    const uint32_t* r1hi = A + (g + 24) * BUF_STRIDE;

#pragma unroll
    for (int k16 = 0; k16 < KC; k16++) {
        int cw = k16 * 8 + q;
        uint32_t a00 = r0lo[cw], a01 = r0hi[cw], a02 = r0lo[cw + 4], a03 = r0hi[cw + 4];
        uint32_t a10 = r1lo[cw], a11 = r1hi[cw], a12 = r1lo[cw + 4], a13 = r1hi[cw + 4];
        const uint2* W2 = Wp + (size_t)(k16 * NTT) * 32 + lane;
#pragma unroll
        for (int n8 = 0; n8 < NTH; n8++) {
            uint2 b = W2[n8 * 32];
            mma16(acc[0][n8], a00, a01, a02, a03, b.x, b.y);
            mma16(acc[1][n8], a10, a11, a12, a13, b.x, b.y);
        }
    }
}

__device__ __forceinline__ int key_of(float4 P) {
    int t = min(127, max(0, (int)((P.w + 1.0f) * 64.0f)));
    int x = min(15,  max(0, (int)((P.x + 1.0f) * 8.0f)));
    int y = min(15,  max(0, (int)((P.y + 1.0f) * 8.0f)));
    int z = min(7,   max(0, (int)((P.z + 1.0f) * 4.0f)));
    return (t << 11) | (x << 7) | (y << 3) | z;
}

// ---- 1. prologue: plane transpose+fp16 cast + key/hist in one kernel ----
__global__ void prephist_kernel(const float* __restrict__ p0, const float* __restrict__ p1,
                                const float* __restrict__ p2, const float* __restrict__ p3,
                                const float4* __restrict__ pts, int n) {
    const int total = 6912000 + n;
    for (int i = blockIdx.x * blockDim.x + threadIdx.x; i < total;
         i += gridDim.x * blockDim.x) {
        if (i < 6912000) {
            int s, base;
            const float* src;
            if (i < 460800)       { s = 0; base = 0;       src = p0; }
            else if (i < 1382400) { s = 1; base = 460800;  src = p1; }
            else if (i < 3225600) { s = 2; base = 1382400; src = p2; }
            else                  { s = 3; base = 3225600; src = p3; }
            int W = 64 << s;
            int li = i - base;
            int c = li & 15;
            int rest = li >> 4;
            int x = rest % W; rest /= W;
            int y = rest % H_RES;
            int p = rest / H_RES;
            g_planes_h[i] = __float2half(src[((p * 16 + c) * H_RES + y) * W + x]);
        } else {
            int j = i - 6912000;
            int k = key_of(pts[j]);
            g_keys[j] = k;
            atomicAdd(&g_hist[k], 1);
        }
    }
}

// ---- 2-4. scans (verified R9) ----
__global__ void scan1_kernel() {
    __shared__ int s[256];
    int t = threadIdx.x;
    s[t] = g_hist[blockIdx.x * 256 + t];
    __syncthreads();
    for (int o = 128; o > 0; o >>= 1) {
        if (t < o) s[t] += s[t + o];
        __syncthreads();
    }
    if (t == 0) g_bsum[blockIdx.x] = s[0];
}
__global__ void scan2_kernel() {
    __shared__ int s[1024];
    int t = threadIdx.x;
    int v = g_bsum[t];
    s[t] = v;
    __syncthreads();
    for (int o = 1; o < 1024; o <<= 1) {
        int a = (t >= o) ? s[t - o] : 0;
        __syncthreads();
        s[t] += a;
        __syncthreads();
    }
    g_bsum[t] = s[t] - v;
}
__global__ void scan3_kernel() {
    __shared__ int s[256];
    int t = threadIdx.x;
    int i = blockIdx.x * 256 + t;
    int v = g_hist[i];
    s[t] = v;
    __syncthreads();
    for (int o = 1; o < 256; o <<= 1) {
        int a = (t >= o) ? s[t - o] : 0;
        __syncthreads();
        s[t] += a;
        __syncthreads();
    }
    g_offs[i] = s[t] - v + g_bsum[blockIdx.x];
}

// ---- 5. scatter points; re-zero hist for next replay ----
__global__ void scatter_kernel(const float4* __restrict__ pts, int n) {
    for (int i = blockIdx.x * blockDim.x + threadIdx.x; i < n;
         i += gridDim.x * blockDim.x) {
        int k = g_keys[i];
        int pos = atomicAdd(&g_offs[k], 1);
        g_pts_sorted[pos] = pts[i];
        g_idx[pos] = i;
    }
    for (int j = blockIdx.x * blockDim.x + threadIdx.x; j < NB;
         j += gridDim.x * blockDim.x)
        g_hist[j] = 0;
}

// ---- 6. persistent fused kernel: 8 warp-pairs, sorted points, scattered out ----
__global__ void __launch_bounds__(512, 1) fused_kernel(
    const float*  __restrict__ w0, const float* __restrict__ b0,
    const float*  __restrict__ w1, const float* __restrict__ b1,
    const float*  __restrict__ w2, const float* __restrict__ b2,
    float*        __restrict__ out, int n, int ntiles)
{
    extern __shared__ uint32_t sm[];
    const int tid  = threadIdx.x;
    const int lane = tid & 31;
    const int g    = lane >> 2;
    const int q    = lane & 3;
    const int wrp  = tid >> 5;
    const int pair = wrp >> 1;
    const int half = wrp & 1;
    const int bar  = pair + 1;

    // ---- stage fp16 weights once, fragment-packed uint2 ----
    for (int e = tid; e < 8192; e += 512) {
        const float* W; int K, nt, le;
        if (e < 2048)      { W = w0; K = 64;  nt = 16; le = e; }
        else if (e < 6144) { W = w1; K = 128; nt = 16; le = e - 2048; }
        else               { W = w2; K = 128; nt = 8;  le = e - 6144; }
        int perk = nt * 32;
        int k16 = le / perk;
        int r   = le % perk;
        int n8  = r >> 5;
        int ln  = r & 31;
        int nrow = n8 * 8 + (ln >> 2);
        int kb   = k16 * 16 + 2 * (ln & 3);
        const float* src = W + nrow * K + kb;
        uint2 v = { h2_of(src[0], src[1]), h2_of(src[8], src[9]) };
        ((uint2*)sm)[e] = v;
    }
    __syncthreads();

    uint32_t* buf = sm + OFF_BUF + pair * PAIR_WORDS;   // per-pair [32][68]
    const uint2* Wp0 = (const uint2*)sm         + half * 8 * 32;
    const uint2* Wp1 = (const uint2*)sm + 2048  + half * 8 * 32;
    const uint2* Wp2 = (const uint2*)sm + 6144  + half * 4 * 32;

    const int scale_off[4] = {0, 460800, 1382400, 3225600};

    const int ch4  = lane & 3;
    const int pidx = lane >> 2;

#define PBAR() asm volatile("bar.sync %0, 64;" :: "r"(bar) : "memory")

    for (int t = blockIdx.x; t < ntiles; t += gridDim.x) {
        const int rowb = t * 256 + pair * 32;

        // ---- 1. sampling: 4 lanes/point; fp16 corners; sorted points ----
#pragma unroll
        for (int pass = 0; pass < 2; pass++) {
            const int pr = half * 16 + pass * 8 + pidx;
            int ptc = min(rowb + pr, n - 1);
            float4 P = g_pts_sorted[ptc];

            float fy = (P.w + 1.0f) * 0.5f * (float)(H_RES - 1);
            fy = fminf(fmaxf(fy, 0.0f), (float)(H_RES - 1));
            int   iy0 = (int)floorf(fy);
            int   iy1 = min(iy0 + 1, H_RES - 1);
            float wyv = fy - (float)iy0;
            float coord[3] = {P.x, P.y, P.z};

#pragma unroll
            for (int s = 0; s < 4; s++) {
                const int W = 64 << s;
                float prod[4] = {1.f, 1.f, 1.f, 1.f};
#pragma unroll
                for (int p = 0; p < 3; p++) {
                    float x  = coord[p];
                    float fx = (x + 1.0f) * 0.5f * (float)(W - 1);
                    fx = fminf(fmaxf(fx, 0.0f), (float)(W - 1));
                    int   ix0 = (int)floorf(fx);
                    int   ix1 = min(ix0 + 1, W - 1);
                    float wx  = fx - (float)ix0;

                    const uint2* pb2 = (const uint2*)(g_planes_h + scale_off[s]
                                                      + p * (H_RES * W * 16));
                    uint2 ua = pb2[(iy0 * W + ix0) * 4 + ch4];
                    uint2 ub = pb2[(iy0 * W + ix1) * 4 + ch4];
                    uint2 uc = pb2[(iy1 * W + ix0) * 4 + ch4];
                    uint2 ud = pb2[(iy1 * W + ix1) * 4 + ch4];

                    float w00 = (1.0f - wx) * (1.0f - wyv);
                    float w01 = wx * (1.0f - wyv);
                    float w10 = (1.0f - wx) * wyv;
                    float w11 = wx * wyv;

                    float2 a0 = __half22float2(*(const __half2*)&ua.x);
                    float2 a1 = __half22float2(*(const __half2*)&ua.y);
                    float2 b0f = __half22float2(*(const __half2*)&ub.x);
                    float2 b1f = __half22float2(*(const __half2*)&ub.y);
                    float2 c0 = __half22float2(*(const __half2*)&uc.x);
                    float2 c1 = __half22float2(*(const __half2*)&uc.y);
                    float2 d0 = __half22float2(*(const __half2*)&ud.x);
                    float2 d1 = __half22float2(*(const __half2*)&ud.y);

                    prod[0] *= a0.x*w00 + b0f.x*w01 + c0.x*w10 + d0.x*w11;
                    prod[1] *= a0.y*w00 + b0f.y*w01 + c0.y*w10 + d0.y*w11;
                    prod[2] *= a1.x*w00 + b1f.x*w01 + c1.x*w10 + d1.x*w11;
                    prod[3] *= a1.y*w00 + b1f.y*w01 + c1.y*w10 + d1.y*w11;
                }
                uint2 v = { h2_of(prod[0], prod[1]), h2_of(prod[2], prod[3]) };
                *(uint2*)(buf + pr * BUF_STRIDE + s * 8 + ch4 * 2) = v;
            }
        }
        PBAR();

        // ---- 2. layer0 ----
        float acc[2][8][4];
        gemm2m<4, 16, 8>(buf, Wp0, g, q, lane, acc);
        PBAR();

        // ---- 3. epilogue0 ----
#pragma unroll
        for (int n8 = 0; n8 < 8; n8++) {
            int col = (half * 8 + n8) * 8 + 2 * q;
            int w   = (half * 8 + n8) * 4 + q;
            float bb0 = __ldg(b0 + col), bb1 = __ldg(b0 + col + 1);
#pragma unroll
            for (int mt = 0; mt < 2; mt++) {
                buf[(mt * 16 + g) * BUF_STRIDE + w] =
                    h2_of(fmaxf(acc[mt][n8][0] + bb0, 0.f), fmaxf(acc[mt][n8][1] + bb1, 0.f));
                buf[(mt * 16 + g + 8) * BUF_STRIDE + w] =
                    h2_of(fmaxf(acc[mt][n8][2] + bb0, 0.f), fmaxf(acc[mt][n8][3] + bb1, 0.f));
            }
        }
        PBAR();

        // ---- 4. layer1 ----
        gemm2m<8, 16, 8>(buf, Wp1, g, q, lane, acc);
        PBAR();

        // ---- 5. epilogue1 ----
#pragma unroll
        for (int n8 = 0; n8 < 8; n8++) {
            int col = (half * 8 + n8) * 8 + 2 * q;
            int w   = (half * 8 + n8) * 4 + q;
            float bb0 = __ldg(b1 + col), bb1 = __ldg(b1 + col + 1);
#pragma unroll
            for (int mt = 0; mt < 2; mt++) {
                buf[(mt * 16 + g) * BUF_STRIDE + w] =
                    h2_of(fmaxf(acc[mt][n8][0] + bb0, 0.f), fmaxf(acc[mt][n8][1] + bb1, 0.f));
                buf[(mt * 16 + g + 8) * BUF_STRIDE + w] =
                    h2_of(fmaxf(acc[mt][n8][2] + bb0, 0.f), fmaxf(acc[mt][n8][3] + bb1, 0.f));
            }
        }
        PBAR();

        // ---- 6. layer2 + scattered output via g_idx ----
        float acc3[2][4][4];
        gemm2m<8, 8, 4>(buf, Wp2, g, q, lane, acc3);

        int oid[2][2];
#pragma unroll
        for (int mt = 0; mt < 2; mt++) {
            int r = rowb + mt * 16 + g;
            oid[mt][0] = (r < n) ? g_idx[r] : -1;
            oid[mt][1] = (r + 8 < n) ? g_idx[r + 8] : -1;
        }
#pragma unroll
        for (int n8 = 0; n8 < 4; n8++) {
            int col = (half * 4 + n8) * 8 + 2 * q;
            float bb0 = __ldg(b2 + col), bb1 = __ldg(b2 + col + 1);
#pragma unroll
            for (int mt = 0; mt < 2; mt++) {
                if (oid[mt][0] >= 0) {
                    float2 o = { acc3[mt][n8][0] + bb0, acc3[mt][n8][1] + bb1 };
                    *(float2*)(out + (size_t)oid[mt][0] * 64 + col) = o;
                }
                if (oid[mt][1] >= 0) {
                    float2 o = { acc3[mt][n8][2] + bb0, acc3[mt][n8][3] + bb1 };
                    *(float2*)(out + (size_t)oid[mt][1] * 64 + col) = o;
                }
            }
        }
        PBAR();
    }
#undef PBAR
}

extern "C" void kernel_launch(void* const* d_in, const int* in_sizes, int n_in,
                              void* d_out, int out_size) {
    const float* pts = (const float*)d_in[0];
    const float* p0  = (const float*)d_in[1];
    const float* p1  = (const float*)d_in[2];
    const float* p2  = (const float*)d_in[3];
    const float* p3  = (const float*)d_in[4];
    const float* w0  = (const float*)d_in[5];
    const float* b0  = (const float*)d_in[6];
    const float* w1  = (const float*)d_in[7];
    const float* b1  = (const float*)d_in[8];
    const float* w2  = (const float*)d_in[9];
    const float* b2  = (const float*)d_in[10];

    int n = in_sizes[0] / 4;
    int ntiles = (n + 255) / 256;

    int sm_count = 148;
    cudaDeviceGetAttribute(&sm_count, cudaDevAttrMultiProcessorCount, 0);

    cudaFuncSetAttribute(fused_kernel, cudaFuncAttributeMaxDynamicSharedMemorySize, SM_BYTES);

    prephist_kernel<<<8704, 1024>>>(p0, p1, p2, p3, (const float4*)pts, n);
    scan1_kernel<<<1024, 256>>>();
    scan2_kernel<<<1, 1024>>>();
    scan3_kernel<<<1024, 256>>>();
    scatter_kernel<<<2048, 512>>>((const float4*)pts, n);
    fused_kernel<<<sm_count, 512, SM_BYTES>>>(
        w0, b0, w1, b1, w2, b2, (float*)d_out, n, ntiles);
}

// round 12
// speedup vs baseline: 1.1689x; 1.1689x over previous
#include <cuda_runtime.h>
#include <cuda_fp16.h>
#include <cstdint>

#define H_RES 150

// X-paired fp16 planes: per scale s (W = 64<<s), entry (p,y,x) = 32 halfs:
// 4 chunks of 8 halfs: chunk c4 = { corner x  channels c4*4..+3,
//                                   corner x+1 channels c4*4..+3 }  (x+1 clamped)
// scale bases (halfs): 0, 921600, 2764800, 6451200; total 13824000.
__device__ __align__(16) __half g_pp[13824000];

// smem words: fp16 weights [0,16384); per-pair buf [32][68] at 16384 + pair*2176
#define OFF_BUF    16384
#define BUF_STRIDE 68
#define PAIR_WORDS 2176
#define SM_BYTES   135168

__device__ __forceinline__ uint32_t h2_of(float a, float b) {
    __half2 h = __float22half2_rn(make_float2(a, b));   // .x = low half
    return *(uint32_t*)&h;
}

__device__ __forceinline__ void mma16(float d[4], uint32_t a0, uint32_t a1,
                                      uint32_t a2, uint32_t a3,
                                      uint32_t b0, uint32_t b1) {
    asm volatile(
        "mma.sync.aligned.m16n8k16.row.col.f32.f16.f16.f32 "
        "{%0,%1,%2,%3}, {%4,%5,%6,%7}, {%8,%9}, {%0,%1,%2,%3};"
        : "+f"(d[0]), "+f"(d[1]), "+f"(d[2]), "+f"(d[3])
        : "r"(a0), "r"(a1), "r"(a2), "r"(a3), "r"(b0), "r"(b1));
}

// GEMM over 2 m16 tiles and a half-N slice (verified R8/R10 code).
template<int KC, int NTT, int NTH>
__device__ __forceinline__ void gemm2m(const uint32_t* __restrict__ A,
                                       const uint2* __restrict__ Wp,
                                       int g, int q, int lane, float acc[2][NTH][4]) {
#pragma unroll
    for (int mt = 0; mt < 2; mt++)
#pragma unroll
        for (int n8 = 0; n8 < NTH; n8++)
#pragma unroll
            for (int i = 0; i < 4; i++) acc[mt][n8][i] = 0.f;

    const uint32_t* r0lo = A + g * BUF_STRIDE;
    const uint32_t* r0hi = A + (g + 8) * BUF_STRIDE;
    const uint32_t* r1lo = A + (g + 16) * BUF_STRIDE;
    const uint32_t* r1hi = A + (g + 24) * BUF_STRIDE;

#pragma unroll
    for (int k16 = 0; k16 < KC; k16++) {
        int cw = k16 * 8 + q;
        uint32_t a00 = r0lo[cw], a01 = r0hi[cw], a02 = r0lo[cw + 4], a03 = r0hi[cw + 4];
        uint32_t a10 = r1lo[cw], a11 = r1hi[cw], a12 = r1lo[cw + 4], a13 = r1hi[cw + 4];
        const uint2* W2 = Wp + (size_t)(k16 * NTT) * 32 + lane;
#pragma unroll
        for (int n8 = 0; n8 < NTH; n8++) {
            uint2 b = W2[n8 * 32];
            mma16(acc[0][n8], a00, a01, a02, a03, b.x, b.y);
            mma16(acc[1][n8], a10, a11, a12, a13, b.x, b.y);
        }
    }
}

// ---- prologue: build x-paired fp16 planes from [3,16,150,W] fp32 sources ----
__global__ void prep_kernel(const float* __restrict__ p0, const float* __restrict__ p1,
                            const float* __restrict__ p2, const float* __restrict__ p3) {
    const int total = 13824000;
    for (int i = blockIdx.x * blockDim.x + threadIdx.x; i < total;
         i += gridDim.x * blockDim.x) {
        int s, base;
        const float* src;
        if (i < 921600)       { s = 0; base = 0;       src = p0; }
        else if (i < 2764800) { s = 1; base = 921600;  src = p1; }
        else if (i < 6451200) { s = 2; base = 2764800; src = p2; }
        else                  { s = 3; base = 6451200; src = p3; }
        int W = 64 << s;
        int li = i - base;
        int within = li & 31;          // half index within 64B entry
        int ent = li >> 5;
        int c4  = within >> 3;         // channel chunk
        int xs  = (within >> 2) & 1;   // x-corner select
        int chl = within & 3;
        int ch  = c4 * 4 + chl;
        int x = ent % W; ent /= W;
        int y = ent % H_RES;
        int p = ent / H_RES;
        int xcol = min(x + xs, W - 1);
        g_pp[i] = __float2half(src[((p * 16 + ch) * H_RES + y) * W + xcol]);
    }
}

// ---- persistent fused kernel: 8 warp-pairs, pair owns 32 pts, N split across pair ----
__global__ void __launch_bounds__(512, 1) fused_kernel(
    const float4* __restrict__ pts,
    const float*  __restrict__ w0, const float* __restrict__ b0,
    const float*  __restrict__ w1, const float* __restrict__ b1,
    const float*  __restrict__ w2, const float* __restrict__ b2,
    float*        __restrict__ out, int n, int ntiles)
{
    extern __shared__ uint32_t sm[];
    const int tid  = threadIdx.x;
    const int lane = tid & 31;
    const int g    = lane >> 2;
    const int q    = lane & 3;
    const int wrp  = tid >> 5;
    const int pair = wrp >> 1;
    const int half = wrp & 1;
    const int bar  = pair + 1;

    // ---- stage fp16 weights once, fragment-packed uint2 ----
    for (int e = tid; e < 8192; e += 512) {
        const float* W; int K, nt, le;
        if (e < 2048)      { W = w0; K = 64;  nt = 16; le = e; }
        else if (e < 6144) { W = w1; K = 128; nt = 16; le = e - 2048; }
        else               { W = w2; K = 128; nt = 8;  le = e - 6144; }
        int perk = nt * 32;
        int k16 = le / perk;
        int r   = le % perk;
        int n8  = r >> 5;
        int ln  = r & 31;
        int nrow = n8 * 8 + (ln >> 2);
        int kb   = k16 * 16 + 2 * (ln & 3);
        const float* src = W + nrow * K + kb;
        uint2 v = { h2_of(src[0], src[1]), h2_of(src[8], src[9]) };
        ((uint2*)sm)[e] = v;
    }
    __syncthreads();

    uint32_t* buf = sm + OFF_BUF + pair * PAIR_WORDS;   // per-pair [32][68]
    const uint2* Wp0 = (const uint2*)sm         + half * 8 * 32;
    const uint2* Wp1 = (const uint2*)sm + 2048  + half * 8 * 32;
    const uint2* Wp2 = (const uint2*)sm + 6144  + half * 4 * 32;

    const int scale_off[4] = {0, 921600, 2764800, 6451200};

    const int ch4  = lane & 3;    // channel chunk (4 channels)
    const int pidx = lane >> 2;   // point index within pass (0..7)

#define PBAR() asm volatile("bar.sync %0, 64;" :: "r"(bar) : "memory")

    for (int t = blockIdx.x; t < ntiles; t += gridDim.x) {
        const int rowb = t * 256 + pair * 32;

        // ---- 1. sampling: 4 lanes/point; x-paired entries, 2 loads per (s,p) ----
#pragma unroll
        for (int pass = 0; pass < 2; pass++) {
            const int pr = half * 16 + pass * 8 + pidx;
            int ptc = min(rowb + pr, n - 1);
            float4 P = pts[ptc];

            float fy = (P.w + 1.0f) * 0.5f * (float)(H_RES - 1);
            fy = fminf(fmaxf(fy, 0.0f), (float)(H_RES - 1));
            int   iy0 = (int)floorf(fy);
            int   iy1 = min(iy0 + 1, H_RES - 1);
            float wyv = fy - (float)iy0;
            float coord[3] = {P.x, P.y, P.z};

#pragma unroll
            for (int s = 0; s < 4; s++) {
                const int W = 64 << s;
                float prod[4] = {1.f, 1.f, 1.f, 1.f};
#pragma unroll
                for (int p = 0; p < 3; p++) {
                    float x  = coord[p];
                    float fx = (x + 1.0f) * 0.5f * (float)(W - 1);
                    fx = fminf(fmaxf(fx, 0.0f), (float)(W - 1));
                    int   ix0 = (int)floorf(fx);
                    float wx  = fx - (float)ix0;

                    const __half* pb = g_pp + scale_off[s] + p * (H_RES * W * 32);
                    uint4 E0 = *(const uint4*)(pb + (iy0 * W + ix0) * 32 + ch4 * 8);
                    uint4 E1 = *(const uint4*)(pb + (iy1 * W + ix0) * 32 + ch4 * 8);

                    float w00 = (1.0f - wx) * (1.0f - wyv);
                    float w01 = wx * (1.0f - wyv);
                    float w10 = (1.0f - wx) * wyv;
                    float w11 = wx * wyv;

                    float2 a01 = __half22float2(*(const __half2*)&E0.x);  // x0 ch0,1
                    float2 a23 = __half22float2(*(const __half2*)&E0.y);  // x0 ch2,3
                    float2 b01 = __half22float2(*(const __half2*)&E0.z);  // x1 ch0,1
                    float2 b23 = __half22float2(*(const __half2*)&E0.w);  // x1 ch2,3
                    float2 c01 = __half22float2(*(const __half2*)&E1.x);
                    float2 c23 = __half22float2(*(const __half2*)&E1.y);
                    float2 d01 = __half22float2(*(const __half2*)&E1.z);
                    float2 d23 = __half22float2(*(const __half2*)&E1.w);

                    prod[0] *= a01.x*w00 + b01.x*w01 + c01.x*w10 + d01.x*w11;
                    prod[1] *= a01.y*w00 + b01.y*w01 + c01.y*w10 + d01.y*w11;
                    prod[2] *= a23.x*w00 + b23.x*w01 + c23.x*w10 + d23.x*w11;
                    prod[3] *= a23.y*w00 + b23.y*w01 + c23.y*w10 + d23.y*w11;
                }
                uint2 v = { h2_of(prod[0], prod[1]), h2_of(prod[2], prod[3]) };
                *(uint2*)(buf + pr * BUF_STRIDE + s * 8 + ch4 * 2) = v;
            }
        }
        PBAR();

        // ---- 2. layer0: acc = F[32x64] @ w0^T (half-N) ----
        float acc[2][8][4];
        gemm2m<4, 16, 8>(buf, Wp0, g, q, lane, acc);
        PBAR();

        // ---- 3. epilogue0: H(half cols) = fp16(relu(acc + b0)) ----
#pragma unroll
        for (int n8 = 0; n8 < 8; n8++) {
            int col = (half * 8 + n8) * 8 + 2 * q;
            int w   = (half * 8 + n8) * 4 + q;
            float bb0 = __ldg(b0 + col), bb1 = __ldg(b0 + col + 1);
#pragma unroll
            for (int mt = 0; mt < 2; mt++) {
                buf[(mt * 16 + g) * BUF_STRIDE + w] =
                    h2_of(fmaxf(acc[mt][n8][0] + bb0, 0.f), fmaxf(acc[mt][n8][1] + bb1, 0.f));
                buf[(mt * 16 + g + 8) * BUF_STRIDE + w] =
                    h2_of(fmaxf(acc[mt][n8][2] + bb0, 0.f), fmaxf(acc[mt][n8][3] + bb1, 0.f));
            }
        }
        PBAR();

        // ---- 4. layer1: acc = H[32x128] @ w1^T (half-N) ----
        gemm2m<8, 16, 8>(buf, Wp1, g, q, lane, acc);
        PBAR();

        // ---- 5. epilogue1: H(half cols) = fp16(relu(acc + b1)) ----
#pragma unroll
        for (int n8 = 0; n8 < 8; n8++) {
            int col = (half * 8 + n8) * 8 + 2 * q;
            int w   = (half * 8 + n8) * 4 + q;
            float bb0 = __ldg(b1 + col), bb1 = __ldg(b1 + col + 1);
#pragma unroll
            for (int mt = 0; mt < 2; mt++) {
                buf[(mt * 16 + g) * BUF_STRIDE + w] =
                    h2_of(fmaxf(acc[mt][n8][0] + bb0, 0.f), fmaxf(acc[mt][n8][1] + bb1, 0.f));
                buf[(mt * 16 + g + 8) * BUF_STRIDE + w] =
                    h2_of(fmaxf(acc[mt][n8][2] + bb0, 0.f), fmaxf(acc[mt][n8][3] + bb1, 0.f));
            }
        }
        PBAR();

        // ---- 6. layer2: acc3 = H @ w2^T (half of N=64) + output ----
        float acc3[2][4][4];
        gemm2m<8, 8, 4>(buf, Wp2, g, q, lane, acc3);

#pragma unroll
        for (int n8 = 0; n8 < 4; n8++) {
            int col = (half * 4 + n8) * 8 + 2 * q;
            float bb0 = __ldg(b2 + col), bb1 = __ldg(b2 + col + 1);
#pragma unroll
            for (int mt = 0; mt < 2; mt++) {
                int r0 = rowb + mt * 16 + g;
                if (r0 < n) {
                    float2 o = { acc3[mt][n8][0] + bb0, acc3[mt][n8][1] + bb1 };
                    *(float2*)(out + (size_t)r0 * 64 + col) = o;
                }
                if (r0 + 8 < n) {
                    float2 o = { acc3[mt][n8][2] + bb0, acc3[mt][n8][3] + bb1 };
                    *(float2*)(out + (size_t)(r0 + 8) * 64 + col) = o;
                }
            }
        }
        PBAR();   // buf (H) fully consumed before next tile's sampling overwrites
    }
#undef PBAR
}

extern "C" void kernel_launch(void* const* d_in, const int* in_sizes, int n_in,
                              void* d_out, int out_size) {
    const float* pts = (const float*)d_in[0];
    const float* p0  = (const float*)d_in[1];
    const float* p1  = (const float*)d_in[2];
    const float* p2  = (const float*)d_in[3];
    const float* p3  = (const float*)d_in[4];
    const float* w0  = (const float*)d_in[5];
    const float* b0  = (const float*)d_in[6];
    const float* w1  = (const float*)d_in[7];
    const float* b1  = (const float*)d_in[8];
    const float* w2  = (const float*)d_in[9];
    const float* b2  = (const float*)d_in[10];

    int n = in_sizes[0] / 4;
    int ntiles = (n + 255) / 256;

    int sm_count = 148;
    cudaDeviceGetAttribute(&sm_count, cudaDevAttrMultiProcessorCount, 0);

    cudaFuncSetAttribute(fused_kernel, cudaFuncAttributeMaxDynamicSharedMemorySize, SM_BYTES);

    prep_kernel<<<13500, 512>>>(p0, p1, p2, p3);
    fused_kernel<<<sm_count, 512, SM_BYTES>>>(
        (const float4*)pts, w0, b0, w1, b1, w2, b2, (float*)d_out, n, ntiles);
}